// round 1
// baseline (speedup 1.0000x reference)
#include <cuda_runtime.h>
#include <math.h>

// ---------------------------------------------------------------------------
// SelfAttention_39676907883685 — baseline fp32 implementation
//
// Pipeline:
//   1) kv  = x @ w_qk^T                         (8192 x 4096 x 2048)
//   2) s_b = scale * (k0_b^T-access) @ (v_b^T)  (4 x [2048 x 2048 x 2048])
//   3) a   = softmax_rows(s)                    (8192 rows of 2048)
//   4) q_b = a_b @ v_b                          (4 x [2048 x 2048 x 2048])
//   5) out = RowPerm(q) @ w_dense^T + bias      (8192 x 2048 x 2048)
// The reshape/transpose chain of the reference is exactly the row
// permutation: output row c -> q row  b*2048 + h*128 + vh  where
//   h = c & 15, b = (c >> 4) & 3, vh = c >> 6.
// ---------------------------------------------------------------------------

#define BMT 128
#define BNT 128
#define BKT 16

// Scratch (device globals; allocation inside kernel_launch is forbidden)
__device__ float g_kv[(size_t)8192 * 4096];          // 128 MB
__device__ float g_s [(size_t)4 * 2048 * 2048];      //  64 MB
__device__ float g_q [(size_t)4 * 2048 * 2048];      //  64 MB

__device__ __forceinline__ int perm_row(int r) {
    int h  = r & 15;
    int b  = (r >> 4) & 3;
    int vh = r >> 6;
    return b * 2048 + h * 128 + vh;
}

// Generic tiled SGEMM:
//   C[m,n] = alpha * sum_k A[m*sAm + k*sAk] * B[k*sBk + n*sBn]  (+ bias[n])
// A_UNIT_K: sAk == 1 (load 8 contiguous k per thread)
// else:     sAm == 1 (load 8 contiguous m per thread)
// B_UNIT_K: sBk == 1 ; else sBn == 1
// PERM:     A row index is permuted through perm_row (final GEMM only)
template <bool A_UNIT_K, bool B_UNIT_K, bool PERM>
__global__ __launch_bounds__(256) void sgemm_kernel(
    const float* __restrict__ A, const float* __restrict__ B,
    float* __restrict__ C,
    int M, int N, int K,
    long sAm, long sAk, long sBk, long sBn,
    long batchA, long batchB, long batchC,
    float alpha, const float* __restrict__ bias)
{
    __shared__ float As[BKT][BMT];
    __shared__ float Bs[BKT][BNT];

    const int tid = threadIdx.x;
    const int m0 = blockIdx.y * BMT;
    const int n0 = blockIdx.x * BNT;

    A += (long)blockIdx.z * batchA;
    B += (long)blockIdx.z * batchB;
    C += (long)blockIdx.z * batchC;

    float acc[8][8];
#pragma unroll
    for (int i = 0; i < 8; i++)
#pragma unroll
        for (int j = 0; j < 8; j++) acc[i][j] = 0.0f;

    const int tx = tid & 15;   // n-tile
    const int ty = tid >> 4;   // m-tile
    const int t8 = tid * 8;

    for (int k0 = 0; k0 < K; k0 += BKT) {
        // ---- load A tile (BMT x BKT) ----
        if (A_UNIT_K) {
            int m  = t8 >> 4;      // 0..127
            int kk = t8 & 15;      // 0 or 8
            long row = m0 + m;
            if (PERM) row = perm_row((int)row);
            const float4* src = (const float4*)(A + row * sAm + (k0 + kk));
            float4 v0 = src[0], v1 = src[1];
            As[kk + 0][m] = v0.x; As[kk + 1][m] = v0.y;
            As[kk + 2][m] = v0.z; As[kk + 3][m] = v0.w;
            As[kk + 4][m] = v1.x; As[kk + 5][m] = v1.y;
            As[kk + 6][m] = v1.z; As[kk + 7][m] = v1.w;
        } else {
            int m  = t8 & 127;     // multiple of 8
            int kk = t8 >> 7;      // 0..15
            const float4* src = (const float4*)(A + (long)(m0 + m) + (long)(k0 + kk) * sAk);
            float4 v0 = src[0], v1 = src[1];
            *(float4*)&As[kk][m]     = v0;
            *(float4*)&As[kk][m + 4] = v1;
        }
        // ---- load B tile (BKT x BNT) ----
        if (B_UNIT_K) {
            int n  = t8 >> 4;
            int kk = t8 & 15;
            const float4* src = (const float4*)(B + (long)(n0 + n) * sBn + (k0 + kk));
            float4 v0 = src[0], v1 = src[1];
            Bs[kk + 0][n] = v0.x; Bs[kk + 1][n] = v0.y;
            Bs[kk + 2][n] = v0.z; Bs[kk + 3][n] = v0.w;
            Bs[kk + 4][n] = v1.x; Bs[kk + 5][n] = v1.y;
            Bs[kk + 6][n] = v1.z; Bs[kk + 7][n] = v1.w;
        } else {
            int n  = t8 & 127;
            int kk = t8 >> 7;
            const float4* src = (const float4*)(B + (long)(k0 + kk) * sBk + (n0 + n));
            float4 v0 = src[0], v1 = src[1];
            *(float4*)&Bs[kk][n]     = v0;
            *(float4*)&Bs[kk][n + 4] = v1;
        }
        __syncthreads();

#pragma unroll
        for (int kk = 0; kk < BKT; kk++) {
            float4 a0 = *(const float4*)&As[kk][ty * 8];
            float4 a1 = *(const float4*)&As[kk][ty * 8 + 4];
            float4 b0 = *(const float4*)&Bs[kk][tx * 8];
            float4 b1 = *(const float4*)&Bs[kk][tx * 8 + 4];
            float a[8] = {a0.x, a0.y, a0.z, a0.w, a1.x, a1.y, a1.z, a1.w};
            float b[8] = {b0.x, b0.y, b0.z, b0.w, b1.x, b1.y, b1.z, b1.w};
#pragma unroll
            for (int i = 0; i < 8; i++)
#pragma unroll
                for (int j = 0; j < 8; j++)
                    acc[i][j] = fmaf(a[i], b[j], acc[i][j]);
        }
        __syncthreads();
    }

    // ---- epilogue ----
#pragma unroll
    for (int i = 0; i < 8; i++) {
        float* crow = C + (long)(m0 + ty * 8 + i) * N + n0 + tx * 8;
#pragma unroll
        for (int j = 0; j < 8; j++) {
            float v = acc[i][j] * alpha;
            if (bias) v += bias[n0 + tx * 8 + j];
            crow[j] = v;
        }
    }
}

// Row softmax over 2048 elements, one block (256 threads) per row, in-place.
__global__ __launch_bounds__(256) void softmax_kernel(float* __restrict__ s)
{
    const long row = blockIdx.x;
    float* p = s + row * 2048;
    const int tid = threadIdx.x;

    float v[8];
    float mx = -1e30f;
#pragma unroll
    for (int j = 0; j < 8; j++) {
        v[j] = p[tid + j * 256];
        mx = fmaxf(mx, v[j]);
    }

    __shared__ float red[256];
    red[tid] = mx;
    __syncthreads();
#pragma unroll
    for (int st = 128; st > 0; st >>= 1) {
        if (tid < st) red[tid] = fmaxf(red[tid], red[tid + st]);
        __syncthreads();
    }
    mx = red[0];
    __syncthreads();

    float sum = 0.0f;
#pragma unroll
    for (int j = 0; j < 8; j++) {
        v[j] = expf(v[j] - mx);
        sum += v[j];
    }
    red[tid] = sum;
    __syncthreads();
#pragma unroll
    for (int st = 128; st > 0; st >>= 1) {
        if (tid < st) red[tid] += red[tid + st];
        __syncthreads();
    }
    const float inv = 1.0f / red[0];

#pragma unroll
    for (int j = 0; j < 8; j++) p[tid + j * 256] = v[j] * inv;
}

extern "C" void kernel_launch(void* const* d_in, const int* in_sizes, int n_in,
                              void* d_out, int out_size)
{
    const float* x       = (const float*)d_in[0];
    const float* w_qk    = (const float*)d_in[1];
    const float* w_dense = (const float*)d_in[2];
    const float* b_dense = (const float*)d_in[3];
    float* out = (float*)d_out;

    float *kv, *s, *q;
    cudaGetSymbolAddress((void**)&kv, g_kv);
    cudaGetSymbolAddress((void**)&s,  g_s);
    cudaGetSymbolAddress((void**)&q,  g_q);

    const int D = 2048;

    // 1) kv[bt, e] = sum_d x[bt, d] * w_qk[e, d]   (M=8192, N=4096, K=2048)
    {
        dim3 grid(4096 / BNT, 8192 / BMT, 1);
        sgemm_kernel<true, true, false><<<grid, 256>>>(
            x, w_qk, kv, 8192, 4096, 2048,
            /*sAm*/ 2048, /*sAk*/ 1, /*sBk*/ 1, /*sBn*/ 2048,
            0, 0, 0, 1.0f, nullptr);
    }

    // 2) s[b,i,j] = scale * sum_m kv[b,m,i] * kv[b,j,2048+m]
    {
        float alpha = 1.0f / sqrtf((float)((double)D * (D - 1) / 2.0));
        dim3 grid(2048 / BNT, 2048 / BMT, 4);
        sgemm_kernel<false, true, false><<<grid, 256>>>(
            kv, kv + 2048, s, 2048, 2048, 2048,
            /*sAm*/ 1, /*sAk*/ 4096, /*sBk*/ 1, /*sBn*/ 4096,
            (long)2048 * 4096, (long)2048 * 4096, (long)2048 * 2048,
            alpha, nullptr);
    }

    // 3) a = softmax_rows(s), in place
    softmax_kernel<<<8192, 256>>>(s);

    // 4) q[b,i,d] = sum_t a[b,i,t] * kv[b,t,2048+d]
    {
        dim3 grid(2048 / BNT, 2048 / BMT, 4);
        sgemm_kernel<true, false, false><<<grid, 256>>>(
            s, kv + 2048, q, 2048, 2048, 2048,
            /*sAm*/ 2048, /*sAk*/ 1, /*sBk*/ 4096, /*sBn*/ 1,
            (long)2048 * 2048, (long)2048 * 4096, (long)2048 * 2048,
            1.0f, nullptr);
    }

    // 5) out[c, e] = sum_d q[perm(c), d] * w_dense[e, d] + b_dense[e]
    {
        dim3 grid(2048 / BNT, 8192 / BMT, 1);
        sgemm_kernel<true, true, true><<<grid, 256>>>(
            q, w_dense, out, 8192, 2048, 2048,
            /*sAm*/ 2048, /*sAk*/ 1, /*sBk*/ 1, /*sBn*/ 2048,
            0, 0, 0, 1.0f, b_dense);
    }
}

// round 3
// speedup vs baseline: 2.2091x; 2.2091x over previous
#include <cuda_runtime.h>
#include <cuda_bf16.h>
#include <math.h>

// ---------------------------------------------------------------------------
// SelfAttention_39676907883685 — bf16 split-3 tensor-core implementation
//
// Every GEMM is C[m,n] = alpha * sum_k A[m,k]*B[n,k] (+bias), with fp32
// operands split into bf16 (hi, lo) pairs and computed as
//   Ahi*Bhi + Ahi*Blo + Alo*Bhi     (~2^-16 effective precision)
// on mma.sync.m16n8k16 tensor cores.
//
// Pipeline:
//   split(x), split(w_qk), split(w_dense)
//   1) kv  = x @ w_qk^T                           (8192 x 4096 x 2048)
//      split(v = kv[:,2048:]); transpose-split(k0t); transpose-split(vT)
//   2) s_b = scale * k0t_b @ v_b^T                (4 x 2048^3)
//   3) softmax rows; split(a)
//   4) q_b = a_b @ vT_b^T                         (4 x 2048^3)
//      perm-split(qp): row c <- q row b*2048+h*128+vh  (h=c&15,b=(c>>4)&3,vh=c>>6)
//   5) out = qp @ w_dense^T + bias                (8192 x 2048 x 2048)
// ---------------------------------------------------------------------------

typedef unsigned short u16;
typedef unsigned int   u32;

#define BM 128
#define BN 128
#define BK 32
#define ROWB 80                 // padded smem row bytes (40 bf16) -> conflict-free
#define ARR (128 * ROWB)        // 10240 B per tile array
#define STAGE (4 * ARR)         // Ah, Al, Bh, Bl
#define SMEM_TOTAL (2 * STAGE)  // double buffered = 81920 B

// ------------------------------ scratch ------------------------------------
__device__ float g_kv[(size_t)8192 * 4096];
__device__ float g_s [(size_t)4 * 2048 * 2048];
__device__ float g_q [(size_t)4 * 2048 * 2048];

__device__ u16 g_xh [(size_t)8192 * 2048], g_xl [(size_t)8192 * 2048];
__device__ u16 g_wqh[(size_t)4096 * 2048], g_wql[(size_t)4096 * 2048];
__device__ u16 g_k0h[(size_t)4 * 2048 * 2048], g_k0l[(size_t)4 * 2048 * 2048];
__device__ u16 g_vh [(size_t)4 * 2048 * 2048], g_vl [(size_t)4 * 2048 * 2048];
__device__ u16 g_vth[(size_t)4 * 2048 * 2048], g_vtl[(size_t)4 * 2048 * 2048];
__device__ u16 g_ah [(size_t)4 * 2048 * 2048], g_al [(size_t)4 * 2048 * 2048];
__device__ u16 g_qph[(size_t)4 * 2048 * 2048], g_qpl[(size_t)4 * 2048 * 2048];
__device__ u16 g_wdh[(size_t)2048 * 2048], g_wdl[(size_t)2048 * 2048];

// ------------------------------ helpers ------------------------------------
__device__ __forceinline__ void split1(float x, u16& h, u16& l) {
    __nv_bfloat16 bh = __float2bfloat16_rn(x);
    h = __bfloat16_as_ushort(bh);
    float resid = x - __bfloat162float(bh);
    l = __bfloat16_as_ushort(__float2bfloat16_rn(resid));
}

__device__ __forceinline__ void cp16(u32 saddr, const void* gptr) {
    asm volatile("cp.async.cg.shared.global [%0], [%1], 16;\n"
                 :: "r"(saddr), "l"(gptr));
}

__device__ __forceinline__ void ldsm4(u32* r, u32 addr) {
    asm volatile("ldmatrix.sync.aligned.m8n8.x4.shared.b16 {%0,%1,%2,%3}, [%4];\n"
                 : "=r"(r[0]), "=r"(r[1]), "=r"(r[2]), "=r"(r[3]) : "r"(addr));
}

__device__ __forceinline__ void mma16816(float* c, const u32* a, const u32* b) {
    asm volatile(
        "mma.sync.aligned.m16n8k16.row.col.f32.bf16.bf16.f32 "
        "{%0,%1,%2,%3}, {%4,%5,%6,%7}, {%8,%9}, {%0,%1,%2,%3};\n"
        : "+f"(c[0]), "+f"(c[1]), "+f"(c[2]), "+f"(c[3])
        : "r"(a[0]), "r"(a[1]), "r"(a[2]), "r"(a[3]), "r"(b[0]), "r"(b[1]));
}

// ------------------------- conversion kernels ------------------------------
// split a dense [rows x cols] region (row stride ldin) into bf16 hi/lo
__global__ __launch_bounds__(256) void split2d_kernel(
    const float* __restrict__ in, size_t ldin,
    u16* __restrict__ hi, u16* __restrict__ lo, int cols)
{
    size_t idx = (size_t)blockIdx.x * 256 + threadIdx.x;
    int cq = cols >> 2;
    size_t r  = idx / cq;
    size_t c4 = (idx % cq) * 4;
    float4 v = *(const float4*)(in + r * ldin + c4);
    u16 h0, l0, h1, l1, h2, l2, h3, l3;
    split1(v.x, h0, l0); split1(v.y, h1, l1);
    split1(v.z, h2, l2); split1(v.w, h3, l3);
    uint2 ph, pl;
    ph.x = (u32)h0 | ((u32)h1 << 16); ph.y = (u32)h2 | ((u32)h3 << 16);
    pl.x = (u32)l0 | ((u32)l1 << 16); pl.y = (u32)l2 | ((u32)l3 << 16);
    *(uint2*)(hi + r * cols + c4) = ph;
    *(uint2*)(lo + r * cols + c4) = pl;
}

// per-batch 2048x2048 transpose + split: out[z][i][m] = in[z*2048 + m][i]
__global__ __launch_bounds__(256) void transpose_split_kernel(
    const float* __restrict__ in, size_t ldin,
    u16* __restrict__ hi, u16* __restrict__ lo)
{
    __shared__ float t[32][33];
    const float* inb = in + (size_t)blockIdx.z * 2048 * ldin;
    size_t ob = (size_t)blockIdx.z * 2048 * 2048;
    int x0 = blockIdx.x * 32, y0 = blockIdx.y * 32;
    int tx = threadIdx.x, ty = threadIdx.y;  // 32 x 8
#pragma unroll
    for (int j = 0; j < 32; j += 8)
        t[ty + j][tx] = inb[(size_t)(y0 + ty + j) * ldin + x0 + tx];
    __syncthreads();
#pragma unroll
    for (int j = 0; j < 32; j += 8) {
        float v = t[tx][ty + j];
        u16 h, l;
        split1(v, h, l);
        size_t o = ob + (size_t)(x0 + ty + j) * 2048 + y0 + tx;
        hi[o] = h;
        lo[o] = l;
    }
}

// permuted split of q: out row c <- q row ((c>>4)&3)*2048 + (c&15)*128 + (c>>6)
__global__ __launch_bounds__(256) void split_perm_kernel(
    const float* __restrict__ q, u16* __restrict__ hi, u16* __restrict__ lo)
{
    size_t idx = (size_t)blockIdx.x * 256 + threadIdx.x;
    int r  = (int)(idx >> 9);
    int c4 = (int)(idx & 511) * 4;
    int pr = ((r >> 4) & 3) * 2048 + (r & 15) * 128 + (r >> 6);
    float4 v = *(const float4*)(q + (size_t)pr * 2048 + c4);
    u16 h0, l0, h1, l1, h2, l2, h3, l3;
    split1(v.x, h0, l0); split1(v.y, h1, l1);
    split1(v.z, h2, l2); split1(v.w, h3, l3);
    uint2 ph, pl;
    ph.x = (u32)h0 | ((u32)h1 << 16); ph.y = (u32)h2 | ((u32)h3 << 16);
    pl.x = (u32)l0 | ((u32)l1 << 16); pl.y = (u32)l2 | ((u32)l3 << 16);
    *(uint2*)(hi + (size_t)r * 2048 + c4) = ph;
    *(uint2*)(lo + (size_t)r * 2048 + c4) = pl;
}

// ----------------------------- GEMM kernel ---------------------------------
// C[m,n] = alpha * sum_k (Ah+Al)[m,k]*(Bh+Bl)[n,k]  (3-term split) + bias[n]
// A: [M x K] row-major bf16 hi/lo, B: [N x K] row-major bf16 hi/lo, C fp32.
__global__ __launch_bounds__(256) void mma_gemm(
    const u16* __restrict__ Ah, const u16* __restrict__ Al,
    const u16* __restrict__ Bh, const u16* __restrict__ Bl,
    float* __restrict__ C,
    int M, int N, int K,
    size_t bA, size_t bB, size_t bC,
    float alpha, const float* __restrict__ bias)
{
    extern __shared__ char smem[];
    const u32 sbase = (u32)__cvta_generic_to_shared(smem);
    const int tid = threadIdx.x, lane = tid & 31, warp = tid >> 5;
    const int wm = warp & 1, wn = warp >> 1;     // 2 x 4 warp grid (64 x 32 each)
    const size_t z = blockIdx.z;
    Ah += z * bA; Al += z * bA;
    Bh += z * bB; Bl += z * bB;
    C  += z * bC;
    const int m0 = blockIdx.y * BM, n0 = blockIdx.x * BN;

    float acc[4][4][4];
#pragma unroll
    for (int i = 0; i < 4; i++)
#pragma unroll
        for (int j = 0; j < 4; j++)
#pragma unroll
            for (int k = 0; k < 4; k++) acc[i][j][k] = 0.0f;

    // ldmatrix per-lane intra-tile offsets
    const u32 a_off = (u32)((lane & 15) * ROWB + (lane >> 4) * 16);
    const u32 b_off = (u32)(((lane & 7) + ((lane >> 4) << 3)) * ROWB +
                            ((lane >> 3) & 1) * 16);

    const int nk = K / BK;

    // stage loader: 2 16B chunks per thread per array
    auto load_stage = [&](int buf, int k0) {
        u32 sb = sbase + buf * STAGE;
#pragma unroll
        for (int j = 0; j < 2; j++) {
            int cc = tid * 2 + j;
            int rr = cc >> 2, qq = cc & 3;
            size_t ga = (size_t)(m0 + rr) * K + k0 + qq * 8;
            size_t gb = (size_t)(n0 + rr) * K + k0 + qq * 8;
            u32 so = (u32)(rr * ROWB + qq * 16);
            cp16(sb + 0 * ARR + so, Ah + ga);
            cp16(sb + 1 * ARR + so, Al + ga);
            cp16(sb + 2 * ARR + so, Bh + gb);
            cp16(sb + 3 * ARR + so, Bl + gb);
        }
        asm volatile("cp.async.commit_group;\n" ::);
    };

    load_stage(0, 0);

    for (int kt = 0; kt < nk; kt++) {
        asm volatile("cp.async.wait_group 0;\n" ::);
        __syncthreads();
        if (kt + 1 < nk) load_stage((kt + 1) & 1, (kt + 1) * BK);

        u32 sb = sbase + (kt & 1) * STAGE;
#pragma unroll
        for (int ks = 0; ks < 2; ks++) {
            u32 bh[2][4], bl[2][4];
#pragma unroll
            for (int np = 0; np < 2; np++) {
                u32 addr = sb + 2 * ARR + (u32)((wn * 32 + np * 16) * ROWB + ks * 32) + b_off;
                ldsm4(bh[np], addr);
                ldsm4(bl[np], addr + ARR);
            }
#pragma unroll
            for (int mi = 0; mi < 4; mi++) {
                u32 ah[4], al[4];
                u32 addr = sb + (u32)((wm * 64 + mi * 16) * ROWB + ks * 32) + a_off;
                ldsm4(ah, addr);
                ldsm4(al, addr + ARR);
#pragma unroll
                for (int ni = 0; ni < 4; ni++)
                    mma16816(acc[mi][ni], ah, &bh[ni >> 1][(ni & 1) * 2]);
#pragma unroll
                for (int ni = 0; ni < 4; ni++)
                    mma16816(acc[mi][ni], ah, &bl[ni >> 1][(ni & 1) * 2]);
#pragma unroll
                for (int ni = 0; ni < 4; ni++)
                    mma16816(acc[mi][ni], al, &bh[ni >> 1][(ni & 1) * 2]);
            }
        }
    }

    // epilogue
#pragma unroll
    for (int mi = 0; mi < 4; mi++) {
        int row = m0 + wm * 64 + mi * 16 + (lane >> 2);
#pragma unroll
        for (int ni = 0; ni < 4; ni++) {
            int col = n0 + wn * 32 + ni * 8 + (lane & 3) * 2;
            float bb0 = 0.0f, bb1 = 0.0f;
            if (bias) { bb0 = bias[col]; bb1 = bias[col + 1]; }
            float2 v0 = make_float2(acc[mi][ni][0] * alpha + bb0,
                                    acc[mi][ni][1] * alpha + bb1);
            float2 v1 = make_float2(acc[mi][ni][2] * alpha + bb0,
                                    acc[mi][ni][3] * alpha + bb1);
            *(float2*)(C + (size_t)row * N + col) = v0;
            *(float2*)(C + (size_t)(row + 8) * N + col) = v1;
        }
    }
}

// ------------------------------- softmax -----------------------------------
__global__ __launch_bounds__(256) void softmax_kernel(float* __restrict__ s)
{
    const size_t row = blockIdx.x;
    float* p = s + row * 2048;
    const int tid = threadIdx.x;

    float v[8];
    float mx = -1e30f;
#pragma unroll
    for (int j = 0; j < 8; j++) {
        v[j] = p[tid + j * 256];
        mx = fmaxf(mx, v[j]);
    }
    __shared__ float red[256];
    red[tid] = mx;
    __syncthreads();
#pragma unroll
    for (int st = 128; st > 0; st >>= 1) {
        if (tid < st) red[tid] = fmaxf(red[tid], red[tid + st]);
        __syncthreads();
    }
    mx = red[0];
    __syncthreads();

    float sum = 0.0f;
#pragma unroll
    for (int j = 0; j < 8; j++) {
        v[j] = expf(v[j] - mx);
        sum += v[j];
    }
    red[tid] = sum;
    __syncthreads();
#pragma unroll
    for (int st = 128; st > 0; st >>= 1) {
        if (tid < st) red[tid] += red[tid + st];
        __syncthreads();
    }
    const float inv = 1.0f / red[0];
#pragma unroll
    for (int j = 0; j < 8; j++) p[tid + j * 256] = v[j] * inv;
}

// ------------------------------- launch ------------------------------------
extern "C" void kernel_launch(void* const* d_in, const int* in_sizes, int n_in,
                              void* d_out, int out_size)
{
    const float* x       = (const float*)d_in[0];
    const float* w_qk    = (const float*)d_in[1];
    const float* w_dense = (const float*)d_in[2];
    const float* b_dense = (const float*)d_in[3];
    float* out = (float*)d_out;

    float *kv, *s, *q;
    u16 *xh, *xl, *wqh, *wql, *k0h, *k0l, *vh, *vl, *vth, *vtl;
    u16 *ah, *al, *qph, *qpl, *wdh, *wdl;
    cudaGetSymbolAddress((void**)&kv,  g_kv);
    cudaGetSymbolAddress((void**)&s,   g_s);
    cudaGetSymbolAddress((void**)&q,   g_q);
    cudaGetSymbolAddress((void**)&xh,  g_xh);  cudaGetSymbolAddress((void**)&xl,  g_xl);
    cudaGetSymbolAddress((void**)&wqh, g_wqh); cudaGetSymbolAddress((void**)&wql, g_wql);
    cudaGetSymbolAddress((void**)&k0h, g_k0h); cudaGetSymbolAddress((void**)&k0l, g_k0l);
    cudaGetSymbolAddress((void**)&vh,  g_vh);  cudaGetSymbolAddress((void**)&vl,  g_vl);
    cudaGetSymbolAddress((void**)&vth, g_vth); cudaGetSymbolAddress((void**)&vtl, g_vtl);
    cudaGetSymbolAddress((void**)&ah,  g_ah);  cudaGetSymbolAddress((void**)&al,  g_al);
    cudaGetSymbolAddress((void**)&qph, g_qph); cudaGetSymbolAddress((void**)&qpl, g_qpl);
    cudaGetSymbolAddress((void**)&wdh, g_wdh); cudaGetSymbolAddress((void**)&wdl, g_wdl);

    cudaFuncSetAttribute(mma_gemm, cudaFuncAttributeMaxDynamicSharedMemorySize,
                         SMEM_TOTAL);

    const size_t BATCH = (size_t)2048 * 2048;
    const float scale = 1.0f / sqrtf((float)((double)2048 * 2047 / 2.0));

    // split inputs
    split2d_kernel<<<16384, 256>>>(x,       2048, xh,  xl,  2048);
    split2d_kernel<<< 8192, 256>>>(w_qk,    2048, wqh, wql, 2048);
    split2d_kernel<<< 4096, 256>>>(w_dense, 2048, wdh, wdl, 2048);

    // 1) kv = x @ w_qk^T
    mma_gemm<<<dim3(32, 64, 1), 256, SMEM_TOTAL>>>(
        xh, xl, wqh, wql, kv, 8192, 4096, 2048, 0, 0, 0, 1.0f, nullptr);

    // derived operands
    split2d_kernel<<<16384, 256>>>(kv + 2048, 4096, vh, vl, 2048);       // v
    transpose_split_kernel<<<dim3(64, 64, 4), dim3(32, 8)>>>(kv,        4096, k0h, k0l);
    transpose_split_kernel<<<dim3(64, 64, 4), dim3(32, 8)>>>(kv + 2048, 4096, vth, vtl);

    // 2) s = scale * k0t @ v^T  (batched)
    mma_gemm<<<dim3(16, 16, 4), 256, SMEM_TOTAL>>>(
        k0h, k0l, vh, vl, s, 2048, 2048, 2048, BATCH, BATCH, BATCH, scale, nullptr);

    // 3) softmax
    softmax_kernel<<<8192, 256>>>(s);
    split2d_kernel<<<16384, 256>>>(s, 2048, ah, al, 2048);

    // 4) q = a @ vT^T  (batched)
    mma_gemm<<<dim3(16, 16, 4), 256, SMEM_TOTAL>>>(
        ah, al, vth, vtl, q, 2048, 2048, 2048, BATCH, BATCH, BATCH, 1.0f, nullptr);

    // permuted split of q
    split_perm_kernel<<<16384, 256>>>(q, qph, qpl);

    // 5) out = qp @ w_dense^T + bias
    mma_gemm<<<dim3(16, 64, 1), 256, SMEM_TOTAL>>>(
        qph, qpl, wdh, wdl, out, 8192, 2048, 2048, 0, 0, 0, 1.0f, b_dense);
}